// round 14
// baseline (speedup 1.0000x reference)
#include <cuda_runtime.h>
#include <math.h>

#define BB   8
#define TT   8192
#define DD   256
#define KK   8
#define CC   64
#define LL   (TT / CC)       // 128
#define NSEQ (BB * DD)       // 2048
#define TOUT (TT - KK + 1)   // 8185
#define QD   4               // K2 prefetch depth
#define PFD  16              // K1 L2 prefetch distance (steps)
#define XB3  12              // K3 register prefetch depth

// Scratch (static __device__ — no allocation). Scalar layout, coalesced in s.
__device__ float g_trans[CC][36][NSEQ];   // 18.9 MB
__device__ float g_entry[CC][KK][NSEQ];   // 4.2 MB

__host__ __device__ constexpr int coff(int j) { return j * 7 - j * (j - 1) / 2; }

// FFMA with immediate 1.0 multiplier (bit-exact a + c).
#define FMAI(d, a, c) \
    asm("fma.rn.f32 %0, %1, 0f3F800000, %2;" : "=f"(d) : "f"(a), "f"(c))

__device__ __forceinline__ float chainmax(float m, float pred, float f)
{
    float t; FMAI(t, pred, f);
    return fmaxf(m, t);
}

#define PREFETCH_L2(p) \
    asm volatile("prefetch.global.L2 [%0];" :: "l"(p))

#define STG_CS(p, v) \
    asm volatile("st.global.cs.f32 [%0], %1;" :: "l"(p), "f"(v) : "memory")

// ---------------------------------------------------------------------------
// K1: column-split transform (two warps per 32 (chunk,seq) pairs):
//   role 0: local vector v[0..7] + matrix cols 3,4,5,6 (18 states)
//   role 1: matrix cols 0,1,2                          (18 states)
// Row-major update order (one f temp, computed on demand) to minimize
// live registers; 8-deep register prefetch + L2 prefetch.
// ---------------------------------------------------------------------------
__global__ void __launch_bounds__(64, 20) k1_transform(
    const float* __restrict__ X,
    const float* __restrict__ W,
    const float* __restrict__ Bv)
{
    int lane = threadIdx.x & 31;
    int role = threadIdx.x >> 5;
    int pid  = blockIdx.x * 32 + lane;     // 0 .. NSEQ*(CC-1)-1
    int d = pid & (DD - 1);
    int q = pid >> 8;
    int b = q & (BB - 1);
    int c = q >> 3;                        // 0 .. CC-2
    int s = b * DD + d;

    const float NI = -INFINITY;

    float wk[KK], bk[KK];
#pragma unroll
    for (int k = 0; k < KK; k++) {
        wk[k] = __ldg(W + k * DD + d);
        bk[k] = __ldg(Bv + k * DD + d);
    }

    const float* xp = X + ((size_t)b * TT + (size_t)c * LL) * DD + d;

    float xb[8];
#pragma unroll
    for (int j = 0; j < 8; j++) xb[j] = __ldg(xp + (size_t)j * DD);
#pragma unroll
    for (int j = 8; j < PFD; j++) PREFETCH_L2(xp + (size_t)j * DD);
    xp += (size_t)8 * DD;

    if (role == 0) {
        float v[8], m3[4], m4[3], m5[2], m6;
#pragma unroll
        for (int k = 0; k < 8; k++) v[k] = NI;
#pragma unroll
        for (int i = 0; i < 4; i++) m3[i] = NI;
#pragma unroll
        for (int i = 0; i < 3; i++) m4[i] = NI;
        m5[0] = NI; m5[1] = NI; m6 = NI;

        // Row-major: all consumers of f[k], rows descending (reads of row k-1
        // still see previous-step values).
#define A_STEP(x) do {                                                   \
        float f;                                                         \
        f = fmaf((x), wk[7], bk[7]);   /* row 7 */                       \
        v[7]  = chainmax(v[7],  v[6],  f);                               \
        m3[3] = chainmax(m3[3], m3[2], f);                               \
        m4[2] = chainmax(m4[2], m4[1], f);                               \
        m5[1] = chainmax(m5[1], m5[0], f);                               \
        m6    = fmaxf(m6, f);                                            \
        f = fmaf((x), wk[6], bk[6]);   /* row 6 */                       \
        v[6]  = chainmax(v[6],  v[5],  f);                               \
        m3[2] = chainmax(m3[2], m3[1], f);                               \
        m4[1] = chainmax(m4[1], m4[0], f);                               \
        m5[0] = fmaxf(m5[0], f);                                         \
        f = fmaf((x), wk[5], bk[5]);   /* row 5 */                       \
        v[5]  = chainmax(v[5],  v[4],  f);                               \
        m3[1] = chainmax(m3[1], m3[0], f);                               \
        m4[0] = fmaxf(m4[0], f);                                         \
        f = fmaf((x), wk[4], bk[4]);   /* row 4 */                       \
        v[4]  = chainmax(v[4],  v[3],  f);                               \
        m3[0] = fmaxf(m3[0], f);                                         \
        f = fmaf((x), wk[3], bk[3]);                                     \
        v[3]  = chainmax(v[3],  v[2],  f);                               \
        f = fmaf((x), wk[2], bk[2]);                                     \
        v[2]  = chainmax(v[2],  v[1],  f);                               \
        f = fmaf((x), wk[1], bk[1]);                                     \
        v[1]  = chainmax(v[1],  v[0],  f);                               \
        f = fmaf((x), wk[0], bk[0]);                                     \
        v[0]  = fmaxf(v[0], f);                                          \
    } while (0)

        for (int ii = 0; ii < LL - 8; ii += 8) {
#pragma unroll
            for (int j = 0; j < 8; j++) {
                float x = xb[j];
                xb[j] = __ldg(xp + (size_t)j * DD);
                if (ii + 8 + j + (PFD - 8) < LL)
                    PREFETCH_L2(xp + (size_t)(j + PFD - 8) * DD);
                A_STEP(x);
            }
            xp += (size_t)8 * DD;
        }
#pragma unroll
        for (int j = 0; j < 8; j++) A_STEP(xb[j]);

#pragma unroll
        for (int k = 0; k < 8; k++) g_trans[c][k][s] = v[k];
#pragma unroll
        for (int i = 0; i < 4; i++) g_trans[c][8 + coff(3) + i][s] = m3[i];
#pragma unroll
        for (int i = 0; i < 3; i++) g_trans[c][8 + coff(4) + i][s] = m4[i];
#pragma unroll
        for (int i = 0; i < 2; i++) g_trans[c][8 + coff(5) + i][s] = m5[i];
        g_trans[c][8 + coff(6)][s] = m6;
    } else {
        float m0[7], m1[6], m2[5];
#pragma unroll
        for (int i = 0; i < 7; i++) m0[i] = NI;
#pragma unroll
        for (int i = 0; i < 6; i++) m1[i] = NI;
#pragma unroll
        for (int i = 0; i < 5; i++) m2[i] = NI;

#define B_STEP(x) do {                                                   \
        float f;                                                         \
        f = fmaf((x), wk[7], bk[7]);   /* row 7 */                       \
        m0[6] = chainmax(m0[6], m0[5], f);                               \
        m1[5] = chainmax(m1[5], m1[4], f);                               \
        m2[4] = chainmax(m2[4], m2[3], f);                               \
        f = fmaf((x), wk[6], bk[6]);   /* row 6 */                       \
        m0[5] = chainmax(m0[5], m0[4], f);                               \
        m1[4] = chainmax(m1[4], m1[3], f);                               \
        m2[3] = chainmax(m2[3], m2[2], f);                               \
        f = fmaf((x), wk[5], bk[5]);   /* row 5 */                       \
        m0[4] = chainmax(m0[4], m0[3], f);                               \
        m1[3] = chainmax(m1[3], m1[2], f);                               \
        m2[2] = chainmax(m2[2], m2[1], f);                               \
        f = fmaf((x), wk[4], bk[4]);   /* row 4 */                       \
        m0[3] = chainmax(m0[3], m0[2], f);                               \
        m1[2] = chainmax(m1[2], m1[1], f);                               \
        m2[1] = chainmax(m2[1], m2[0], f);                               \
        f = fmaf((x), wk[3], bk[3]);   /* row 3 */                       \
        m0[2] = chainmax(m0[2], m0[1], f);                               \
        m1[1] = chainmax(m1[1], m1[0], f);                               \
        m2[0] = fmaxf(m2[0], f);                                         \
        f = fmaf((x), wk[2], bk[2]);   /* row 2 */                       \
        m0[1] = chainmax(m0[1], m0[0], f);                               \
        m1[0] = fmaxf(m1[0], f);                                         \
        f = fmaf((x), wk[1], bk[1]);   /* row 1 */                       \
        m0[0] = fmaxf(m0[0], f);                                         \
    } while (0)

        for (int ii = 0; ii < LL - 8; ii += 8) {
#pragma unroll
            for (int j = 0; j < 8; j++) {
                float x = xb[j];
                xb[j] = __ldg(xp + (size_t)j * DD);
                if (ii + 8 + j + (PFD - 8) < LL)
                    PREFETCH_L2(xp + (size_t)(j + PFD - 8) * DD);
                B_STEP(x);
            }
            xp += (size_t)8 * DD;
        }
#pragma unroll
        for (int j = 0; j < 8; j++) B_STEP(xb[j]);

#pragma unroll
        for (int i = 0; i < 7; i++) g_trans[c][8 + coff(0) + i][s] = m0[i];
#pragma unroll
        for (int i = 0; i < 6; i++) g_trans[c][8 + coff(1) + i][s] = m1[i];
#pragma unroll
        for (int i = 0; i < 5; i++) g_trans[c][8 + coff(2) + i][s] = m2[i];
    }
}

// ---------------------------------------------------------------------------
// K2: warp-parallel compose. 8 threads per sequence (thread = state k);
// v broadcast via shfl; depth-QD register prefetch hides L2 latency.
// ---------------------------------------------------------------------------
__global__ void __launch_bounds__(128) k2_compose()
{
    int t = blockIdx.x * blockDim.x + threadIdx.x;   // 0 .. NSEQ*8-1
    int k = t & 7;
    int s = t >> 3;
    int lane = threadIdx.x & 31;
    int gbase = lane & 24;
    const float NI = -INFINITY;

    int em[7];
#pragma unroll
    for (int j = 0; j < 7; j++)
        em[j] = 8 + coff(j) + k - j - 1;   // valid only when j < k

    const float* base = (const float*)g_trans;

    float pl[QD];
    float pm[QD][7];
#pragma unroll
    for (int u = 0; u < QD; u++) {
        int c = u;
        bool ok = (c <= CC - 2);
        pl[u] = ok ? __ldg(base + ((size_t)c * 36 + k) * NSEQ + s) : NI;
#pragma unroll
        for (int j = 0; j < 7; j++)
            pm[u][j] = (ok && j < k)
                ? __ldg(base + ((size_t)c * 36 + em[j]) * NSEQ + s) : NI;
    }

    float v = NI;

    for (int cb = 0; cb < CC; cb += QD) {
#pragma unroll
        for (int u = 0; u < QD; u++) {
            int c = cb + u;
            g_entry[c][k][s] = v;
            if (c == CC - 1) return;

            float vj[8];
#pragma unroll
            for (int j = 0; j < 8; j++)
                vj[j] = __shfl_sync(0xffffffffu, v, gbase + j);

            float nv = fmaxf(pl[u], v);
#pragma unroll
            for (int j = 0; j < 7; j++)
                nv = fmaxf(nv, vj[j] + pm[u][j]);
            v = nv;

            int cn = c + QD;
            bool ok = (cn <= CC - 2);
            pl[u] = ok ? __ldg(base + ((size_t)cn * 36 + k) * NSEQ + s) : NI;
#pragma unroll
            for (int j = 0; j < 7; j++)
                pm[u][j] = (ok && j < k)
                    ? __ldg(base + ((size_t)cn * 36 + em[j]) * NSEQ + s) : NI;
        }
    }
}

// ---------------------------------------------------------------------------
// K3: scalar re-scan, one thread per (chunk, seq); 12-deep x prefetch;
// streaming (evict-first) output stores.
// ---------------------------------------------------------------------------
__device__ __forceinline__ void scan_step(float x, const float* wk,
                                          const float* bk, float* v)
{
    float f[KK];
#pragma unroll
    for (int k = 0; k < KK; k++) f[k] = fmaf(x, wk[k], bk[k]);
#pragma unroll
    for (int k = KK - 1; k >= 1; k--) v[k] = chainmax(v[k], v[k - 1], f[k]);
    v[0] = fmaxf(v[0], f[0]);
}

__global__ void __launch_bounds__(64) k3_emit(
    const float* __restrict__ X,
    const float* __restrict__ W,
    const float* __restrict__ Bv,
    float* __restrict__ out)
{
    int tid = blockIdx.x * blockDim.x + threadIdx.x;   // 0 .. NSEQ*CC-1
    int d = tid & (DD - 1);
    int q = tid >> 8;
    int b = q & (BB - 1);
    int c = q >> 3;
    int s = b * DD + d;

    float wk[KK], bk[KK];
#pragma unroll
    for (int k = 0; k < KK; k++) {
        wk[k] = __ldg(W + k * DD + d);
        bk[k] = __ldg(Bv + k * DD + d);
    }

    float v[KK];
#pragma unroll
    for (int k = 0; k < KK; k++) v[k] = g_entry[c][k][s];

    const float* xp = X + ((size_t)b * TT + (size_t)c * LL) * DD + d;

    // XB3-deep register prefetch (LL=128 divisible by XB3? use 2 loops of 4 within 12-tile)
    float xb[XB3];
#pragma unroll
    for (int j = 0; j < XB3; j++) xb[j] = __ldg(xp + (size_t)j * DD);
    xp += (size_t)XB3 * DD;

    // LL=128: process 116 steps in the pipelined loop (4-step granularity), 12 in drain.
    if (c == 0) {
        float* ob = out + (size_t)b * TOUT * DD + d;
        int i = 0;
        for (int ii = 0; ii < LL - XB3; ii += 4) {
#pragma unroll
            for (int j = 0; j < 4; j++) {
                int sl = (ii + j) % XB3;
                float x = xb[sl];
                xb[sl] = __ldg(xp + (size_t)j * DD);
                scan_step(x, wk, bk, v);
                if (i >= KK - 1) STG_CS(ob + (size_t)(i - (KK - 1)) * DD, v[KK - 1]);
                i++;
            }
            xp += (size_t)4 * DD;
        }
#pragma unroll
        for (int j = 0; j < XB3; j++) {
            int sl = (LL - XB3 + j) % XB3;
            scan_step(xb[sl], wk, bk, v);
            STG_CS(ob + (size_t)(i - (KK - 1)) * DD, v[KK - 1]);
            i++;
        }
    } else {
        float* op = out + ((size_t)b * TOUT + (size_t)(c * LL - (KK - 1))) * DD + d;
        int i = 0;
        for (int ii = 0; ii < LL - XB3; ii += 4) {
#pragma unroll
            for (int j = 0; j < 4; j++) {
                int sl = (ii + j) % XB3;
                float x = xb[sl];
                xb[sl] = __ldg(xp + (size_t)j * DD);
                scan_step(x, wk, bk, v);
                STG_CS(op + (size_t)i * DD, v[KK - 1]);
                i++;
            }
            xp += (size_t)4 * DD;
        }
#pragma unroll
        for (int j = 0; j < XB3; j++) {
            int sl = (LL - XB3 + j) % XB3;
            scan_step(xb[sl], wk, bk, v);
            STG_CS(op + (size_t)i * DD, v[KK - 1]);
            i++;
        }
    }
}

// ---------------------------------------------------------------------------
extern "C" void kernel_launch(void* const* d_in, const int* in_sizes, int n_in,
                              void* d_out, int out_size)
{
    const float* X  = (const float*)d_in[0];
    const float* W  = (const float*)d_in[1];
    const float* Bv = (const float*)d_in[2];
    float* out = (float*)d_out;

    k1_transform<<<(NSEQ * (CC - 1)) / 32, 64>>>(X, W, Bv);
    k2_compose<<<(NSEQ * 8) / 128, 128>>>();
    k3_emit<<<(NSEQ * CC) / 64, 64>>>(X, W, Bv, out);
}

// round 15
// speedup vs baseline: 1.6012x; 1.6012x over previous
#include <cuda_runtime.h>
#include <math.h>

#define BB   8
#define TT   8192
#define DD   256
#define KK   8
#define CC   64
#define LL   (TT / CC)       // 128
#define NSEQ (BB * DD)       // 2048
#define TOUT (TT - KK + 1)   // 8185
#define QD   4               // K2 prefetch depth
#define PFD  16              // L2 prefetch distance (steps)

// Scratch (static __device__ — no allocation). Scalar layout, coalesced in s.
__device__ float g_trans[CC][36][NSEQ];   // 18.9 MB
__device__ float g_entry[CC][KK][NSEQ];   // 4.2 MB

__host__ __device__ constexpr int coff(int j) { return j * 7 - j * (j - 1) / 2; }

// FFMA with immediate 1.0 multiplier (bit-exact a + c).
#define FMAI(d, a, c) \
    asm("fma.rn.f32 %0, %1, 0f3F800000, %2;" : "=f"(d) : "f"(a), "f"(c))

__device__ __forceinline__ float chainmax(float m, float pred, float f)
{
    float t; FMAI(t, pred, f);
    return fmaxf(m, t);
}

#define PREFETCH_L2(p) \
    asm volatile("prefetch.global.L2 [%0];" :: "l"(p))

#define STG_CS_V2(p, a, b_) \
    asm volatile("st.global.cs.v2.f32 [%0], {%1, %2};" :: "l"(p), "f"(a), "f"(b_) : "memory")

// ---------------------------------------------------------------------------
// K1: column-split transform (two warps per 32 (chunk,seq) pairs):
//   role 0: local vector v[0..7] + matrix cols 3,4,5,6 (18 states)
//   role 1: matrix cols 0,1,2                          (18 states)
// 8-deep register prefetch + 16-step-ahead L2 prefetch. (R12 verbatim.)
// ---------------------------------------------------------------------------
__global__ void __launch_bounds__(64) k1_transform(
    const float* __restrict__ X,
    const float* __restrict__ W,
    const float* __restrict__ Bv)
{
    int lane = threadIdx.x & 31;
    int role = threadIdx.x >> 5;
    int pid  = blockIdx.x * 32 + lane;     // 0 .. NSEQ*(CC-1)-1
    int d = pid & (DD - 1);
    int q = pid >> 8;
    int b = q & (BB - 1);
    int c = q >> 3;                        // 0 .. CC-2
    int s = b * DD + d;

    const float NI = -INFINITY;

    float wk[KK], bk[KK];
#pragma unroll
    for (int k = 0; k < KK; k++) {
        wk[k] = __ldg(W + k * DD + d);
        bk[k] = __ldg(Bv + k * DD + d);
    }

    const float* xp = X + ((size_t)b * TT + (size_t)c * LL) * DD + d;

    float xb[8];
#pragma unroll
    for (int j = 0; j < 8; j++) xb[j] = __ldg(xp + (size_t)j * DD);
#pragma unroll
    for (int j = 8; j < PFD; j++) PREFETCH_L2(xp + (size_t)j * DD);
    xp += (size_t)8 * DD;

    if (role == 0) {
        float v[8], m3[4], m4[3], m5[2], m6;
#pragma unroll
        for (int k = 0; k < 8; k++) v[k] = NI;
#pragma unroll
        for (int i = 0; i < 4; i++) m3[i] = NI;
#pragma unroll
        for (int i = 0; i < 3; i++) m4[i] = NI;
        m5[0] = NI; m5[1] = NI; m6 = NI;

#define A_STEP(x) do {                                                   \
        float f[8];                                                      \
        _Pragma("unroll")                                                \
        for (int k = 0; k < 8; k++) f[k] = fmaf((x), wk[k], bk[k]);      \
        _Pragma("unroll")                                                \
        for (int k = 7; k >= 1; k--) v[k] = chainmax(v[k], v[k-1], f[k]); \
        v[0] = fmaxf(v[0], f[0]);                                        \
        m3[3] = chainmax(m3[3], m3[2], f[7]);                            \
        m3[2] = chainmax(m3[2], m3[1], f[6]);                            \
        m3[1] = chainmax(m3[1], m3[0], f[5]);                            \
        m3[0] = fmaxf(m3[0], f[4]);                                      \
        m4[2] = chainmax(m4[2], m4[1], f[7]);                            \
        m4[1] = chainmax(m4[1], m4[0], f[6]);                            \
        m4[0] = fmaxf(m4[0], f[5]);                                      \
        m5[1] = chainmax(m5[1], m5[0], f[7]);                            \
        m5[0] = fmaxf(m5[0], f[6]);                                      \
        m6    = fmaxf(m6, f[7]);                                         \
    } while (0)

        for (int ii = 0; ii < LL - 8; ii += 8) {
#pragma unroll
            for (int j = 0; j < 8; j++) {
                float x = xb[j];
                xb[j] = __ldg(xp + (size_t)j * DD);
                if (ii + 8 + j + (PFD - 8) < LL)
                    PREFETCH_L2(xp + (size_t)(j + PFD - 8) * DD);
                A_STEP(x);
            }
            xp += (size_t)8 * DD;
        }
#pragma unroll
        for (int j = 0; j < 8; j++) A_STEP(xb[j]);

#pragma unroll
        for (int k = 0; k < 8; k++) g_trans[c][k][s] = v[k];
#pragma unroll
        for (int i = 0; i < 4; i++) g_trans[c][8 + coff(3) + i][s] = m3[i];
#pragma unroll
        for (int i = 0; i < 3; i++) g_trans[c][8 + coff(4) + i][s] = m4[i];
#pragma unroll
        for (int i = 0; i < 2; i++) g_trans[c][8 + coff(5) + i][s] = m5[i];
        g_trans[c][8 + coff(6)][s] = m6;
    } else {
        float m0[7], m1[6], m2[5];
#pragma unroll
        for (int i = 0; i < 7; i++) m0[i] = NI;
#pragma unroll
        for (int i = 0; i < 6; i++) m1[i] = NI;
#pragma unroll
        for (int i = 0; i < 5; i++) m2[i] = NI;

#define B_STEP(x) do {                                                   \
        float f[8];                                                      \
        _Pragma("unroll")                                                \
        for (int k = 1; k < 8; k++) f[k] = fmaf((x), wk[k], bk[k]);      \
        _Pragma("unroll")                                                \
        for (int i = 6; i >= 1; i--) m0[i] = chainmax(m0[i], m0[i-1], f[i+1]); \
        m0[0] = fmaxf(m0[0], f[1]);                                      \
        _Pragma("unroll")                                                \
        for (int i = 5; i >= 1; i--) m1[i] = chainmax(m1[i], m1[i-1], f[i+2]); \
        m1[0] = fmaxf(m1[0], f[2]);                                      \
        _Pragma("unroll")                                                \
        for (int i = 4; i >= 1; i--) m2[i] = chainmax(m2[i], m2[i-1], f[i+3]); \
        m2[0] = fmaxf(m2[0], f[3]);                                      \
    } while (0)

        for (int ii = 0; ii < LL - 8; ii += 8) {
#pragma unroll
            for (int j = 0; j < 8; j++) {
                float x = xb[j];
                xb[j] = __ldg(xp + (size_t)j * DD);
                if (ii + 8 + j + (PFD - 8) < LL)
                    PREFETCH_L2(xp + (size_t)(j + PFD - 8) * DD);
                B_STEP(x);
            }
            xp += (size_t)8 * DD;
        }
#pragma unroll
        for (int j = 0; j < 8; j++) B_STEP(xb[j]);

#pragma unroll
        for (int i = 0; i < 7; i++) g_trans[c][8 + coff(0) + i][s] = m0[i];
#pragma unroll
        for (int i = 0; i < 6; i++) g_trans[c][8 + coff(1) + i][s] = m1[i];
#pragma unroll
        for (int i = 0; i < 5; i++) g_trans[c][8 + coff(2) + i][s] = m2[i];
    }
}

// ---------------------------------------------------------------------------
// K2: warp-parallel compose (R12 verbatim).
// ---------------------------------------------------------------------------
__global__ void __launch_bounds__(128) k2_compose()
{
    int t = blockIdx.x * blockDim.x + threadIdx.x;   // 0 .. NSEQ*8-1
    int k = t & 7;
    int s = t >> 3;
    int lane = threadIdx.x & 31;
    int gbase = lane & 24;
    const float NI = -INFINITY;

    int em[7];
#pragma unroll
    for (int j = 0; j < 7; j++)
        em[j] = 8 + coff(j) + k - j - 1;   // valid only when j < k

    const float* base = (const float*)g_trans;

    float pl[QD];
    float pm[QD][7];
#pragma unroll
    for (int u = 0; u < QD; u++) {
        int c = u;
        bool ok = (c <= CC - 2);
        pl[u] = ok ? __ldg(base + ((size_t)c * 36 + k) * NSEQ + s) : NI;
#pragma unroll
        for (int j = 0; j < 7; j++)
            pm[u][j] = (ok && j < k)
                ? __ldg(base + ((size_t)c * 36 + em[j]) * NSEQ + s) : NI;
    }

    float v = NI;

    for (int cb = 0; cb < CC; cb += QD) {
#pragma unroll
        for (int u = 0; u < QD; u++) {
            int c = cb + u;
            g_entry[c][k][s] = v;
            if (c == CC - 1) return;

            float vj[8];
#pragma unroll
            for (int j = 0; j < 8; j++)
                vj[j] = __shfl_sync(0xffffffffu, v, gbase + j);

            float nv = fmaxf(pl[u], v);
#pragma unroll
            for (int j = 0; j < 7; j++)
                nv = fmaxf(nv, vj[j] + pm[u][j]);
            v = nv;

            int cn = c + QD;
            bool ok = (cn <= CC - 2);
            pl[u] = ok ? __ldg(base + ((size_t)cn * 36 + k) * NSEQ + s) : NI;
#pragma unroll
            for (int j = 0; j < 7; j++)
                pm[u][j] = (ok && j < k)
                    ? __ldg(base + ((size_t)cn * 36 + em[j]) * NSEQ + s) : NI;
        }
    }
}

// ---------------------------------------------------------------------------
// K3: re-scan, TWO adjacent sequences (d, d+1) per thread, scalar math,
// float2 loads/stores; 8-deep prefetch + L2 prefetch; streaming stores.
// ---------------------------------------------------------------------------
__global__ void __launch_bounds__(128) k3_emit(
    const float* __restrict__ X,
    const float* __restrict__ W,
    const float* __restrict__ Bv,
    float* __restrict__ out)
{
    int tid = blockIdx.x * blockDim.x + threadIdx.x;   // 0 .. NSEQ/2*CC-1
    int d = (tid & 127) << 1;          // even d; thread covers d, d+1
    int q = tid >> 7;
    int b = q & (BB - 1);
    int c = q >> 3;
    int s = b * DD + d;

    float wa[KK], ba[KK], wb[KK], bb[KK];
#pragma unroll
    for (int k = 0; k < KK; k++) {
        float2 wv = __ldg((const float2*)(W  + k * DD + d));
        float2 bv = __ldg((const float2*)(Bv + k * DD + d));
        wa[k] = wv.x; wb[k] = wv.y;
        ba[k] = bv.x; bb[k] = bv.y;
    }

    float va[KK], vb[KK];
#pragma unroll
    for (int k = 0; k < KK; k++) {
        float2 ev = __ldg((const float2*)(&g_entry[c][k][s]));
        va[k] = ev.x; vb[k] = ev.y;
    }

    const float* xp = X + ((size_t)b * TT + (size_t)c * LL) * DD + d;

    float2 xb[8];
#pragma unroll
    for (int j = 0; j < 8; j++) xb[j] = __ldg((const float2*)(xp + (size_t)j * DD));
#pragma unroll
    for (int j = 8; j < PFD; j++) PREFETCH_L2(xp + (size_t)j * DD);
    xp += (size_t)8 * DD;

#define K3_STEP(x2) do {                                                  \
        float fa, fb;                                                     \
        _Pragma("unroll")                                                 \
        for (int k = KK - 1; k >= 1; k--) {                               \
            fa = fmaf((x2).x, wa[k], ba[k]);                              \
            fb = fmaf((x2).y, wb[k], bb[k]);                              \
            va[k] = chainmax(va[k], va[k - 1], fa);                       \
            vb[k] = chainmax(vb[k], vb[k - 1], fb);                       \
        }                                                                 \
        fa = fmaf((x2).x, wa[0], ba[0]);                                  \
        fb = fmaf((x2).y, wb[0], bb[0]);                                  \
        va[0] = fmaxf(va[0], fa);                                         \
        vb[0] = fmaxf(vb[0], fb);                                         \
    } while (0)

    if (c == 0) {
        float* ob = out + (size_t)b * TOUT * DD + d;
        for (int ii = 0; ii < LL - 8; ii += 8) {
#pragma unroll
            for (int j = 0; j < 8; j++) {
                float2 x2 = xb[j];
                xb[j] = __ldg((const float2*)(xp + (size_t)j * DD));
                if (ii + 8 + j + (PFD - 8) < LL)
                    PREFETCH_L2(xp + (size_t)(j + PFD - 8) * DD);
                K3_STEP(x2);
                int i = ii + j;
                if (i >= KK - 1)
                    STG_CS_V2(ob + (size_t)(i - (KK - 1)) * DD, va[KK - 1], vb[KK - 1]);
            }
            xp += (size_t)8 * DD;
        }
#pragma unroll
        for (int j = 0; j < 8; j++) {
            K3_STEP(xb[j]);
            STG_CS_V2(ob + (size_t)(LL - 8 + j - (KK - 1)) * DD, va[KK - 1], vb[KK - 1]);
        }
    } else {
        float* op = out + ((size_t)b * TOUT + (size_t)(c * LL - (KK - 1))) * DD + d;
        for (int ii = 0; ii < LL - 8; ii += 8) {
#pragma unroll
            for (int j = 0; j < 8; j++) {
                float2 x2 = xb[j];
                xb[j] = __ldg((const float2*)(xp + (size_t)j * DD));
                if (ii + 8 + j + (PFD - 8) < LL)
                    PREFETCH_L2(xp + (size_t)(j + PFD - 8) * DD);
                K3_STEP(x2);
                STG_CS_V2(op + (size_t)(ii + j) * DD, va[KK - 1], vb[KK - 1]);
            }
            xp += (size_t)8 * DD;
        }
#pragma unroll
        for (int j = 0; j < 8; j++) {
            K3_STEP(xb[j]);
            STG_CS_V2(op + (size_t)(LL - 8 + j) * DD, va[KK - 1], vb[KK - 1]);
        }
    }
}

// ---------------------------------------------------------------------------
extern "C" void kernel_launch(void* const* d_in, const int* in_sizes, int n_in,
                              void* d_out, int out_size)
{
    const float* X  = (const float*)d_in[0];
    const float* W  = (const float*)d_in[1];
    const float* Bv = (const float*)d_in[2];
    float* out = (float*)d_out;

    k1_transform<<<(NSEQ * (CC - 1)) / 32, 64>>>(X, W, Bv);
    k2_compose<<<(NSEQ * 8) / 128, 128>>>();
    k3_emit<<<(NSEQ / 2 * CC) / 128, 128>>>(X, W, Bv, out);
}